// round 16
// baseline (speedup 1.0000x reference)
#include <cuda_runtime.h>
#include <cuda_fp16.h>
#include <math.h>
#include <stdint.h>

#define BB 4
#define SS 2048
#define DD 1024
#define EE 8
#define K2 2048
#define EPSV 1e-6f
#define NCHUNK 16
#define CHUNK (SS / NCHUNK)   // 128

// ---------------- GEMM tiling (fp16 operands) ----------------
#define BM 128
#define BK 64                     // halves per K-chunk (128 bytes/row)
#define NKC (DD / BK)             // 16
#define SPADH 72                  // smem row stride in halves (64 + 8)
#define A_STAGE_HALVES (BM * SPADH)              // 9216
#define NSTAGE 3

// ---------------- scratch ----------------
__device__ __half  g_x[BB * SS * DD];
__device__ float   g_xmean[BB * DD];
__device__ float   g_probs[BB * EE];
__device__ __half  g_Whg[BB * K2 * DD];    // row-permuted: 2j=hidden_j, 2j+1=gate_j
__device__ __half  g_Wout[BB * DD * DD];
__device__ __half2 g_hg2[BB * SS * DD];    // (hidden, gate) per (row, j)
__device__ __half  g_h[BB * SS * DD];
__device__ float   g_chunkC[BB * NCHUNK * DD];
__device__ float   g_chunkH[BB * NCHUNK * DD];
__device__ float   g_hin[BB * NCHUNK * DD];

// ---------------- helpers ----------------
__device__ __forceinline__ uint32_t smem_u32(const void* p) {
    uint32_t a;
    asm("{ .reg .u64 t; cvta.to.shared.u64 t, %1; cvt.u32.u64 %0, t; }" : "=r"(a) : "l"(p));
    return a;
}
__device__ __forceinline__ void cpasync16(uint32_t dst, const void* src) {
    asm volatile("cp.async.cg.shared.global [%0], [%1], 16;" :: "r"(dst), "l"(src));
}
// c = sigmoid(-gate); v = sigmoid(gate) * (hidden>=0 ? hidden+0.5 : sigmoid(hidden))
__device__ __forceinline__ void cv_from_hg(float hidden, float gate, float& c, float& v) {
    float t = expf(-fabsf(gate));
    float inv = 1.0f / (1.0f + t);
    float sp;
    if (gate >= 0.f) { sp = inv; c = t * inv; }
    else             { sp = t * inv; c = inv; }
    float gh = (hidden >= 0.f) ? (hidden + 0.5f) : (1.0f / (1.0f + expf(-hidden)));
    v = sp * gh;
}
__device__ __forceinline__ void cv_from_h2(__half2 hg, float& c, float& v) {
    cv_from_hg(__low2float(hg), __high2float(hg), c, v);
}

// ---------------- 1. RMSNorm (writes fp16 x) ----------------
__global__ void rmsnorm_kernel(const float* __restrict__ inp, const float* __restrict__ nw) {
    int row = blockIdx.x;
    const float* in = inp + (long)row * DD;
    __half* out = g_x + (long)row * DD;
    float ss = 0.f;
    for (int d = threadIdx.x; d < DD; d += 256) { float t = in[d]; ss += t * t; }
    __shared__ float red[256];
    red[threadIdx.x] = ss; __syncthreads();
    for (int s = 128; s > 0; s >>= 1) {
        if (threadIdx.x < s) red[threadIdx.x] += red[threadIdx.x + s];
        __syncthreads();
    }
    float scale = rsqrtf(red[0] * (1.0f / DD) + EPSV);
    for (int d = threadIdx.x; d < DD; d += 256) out[d] = __float2half_rn(in[d] * scale * nw[d]);
}

// ---------------- 2. column mean ----------------
__global__ void colmean_kernel() {
    int t = blockIdx.x * blockDim.x + threadIdx.x;
    if (t >= BB * DD) return;
    int b = t / DD, d = t % DD;
    float s = 0.f;
    const __half* base = g_x + (long)b * SS * DD + d;
    for (int i = 0; i < SS; i++) s += __half2float(base[(long)i * DD]);
    g_xmean[t] = s * (1.0f / SS);
}

// ---------------- 3. router ----------------
__global__ void router_kernel(const float* __restrict__ rw, const float* __restrict__ rb) {
    __shared__ float logits[BB * EE];
    int tid = threadIdx.x, warp = tid / 32, lane = tid % 32;
    for (int p = warp; p < BB * EE; p += 8) {
        int b = p / EE, e = p % EE;
        float s = 0.f;
        for (int d = lane; d < DD; d += 32) s += g_xmean[b * DD + d] * rw[e * DD + d];
        for (int o = 16; o > 0; o >>= 1) s += __shfl_xor_sync(0xffffffffu, s, o);
        if (lane == 0) logits[p] = s + rb[e];
    }
    __syncthreads();
    if (tid < BB) {
        float mx = -1e30f;
        for (int e = 0; e < EE; e++) mx = fmaxf(mx, logits[tid * EE + e]);
        float ex[EE]; float sum = 0.f;
        for (int e = 0; e < EE; e++) { ex[e] = expf(logits[tid * EE + e] - mx); sum += ex[e]; }
        float inv = 1.0f / sum;
        for (int e = 0; e < EE; e++) g_probs[tid * EE + e] = ex[e] * inv;
    }
}

// ---------------- 4. mix expert weights (fp32 accum, fp16 out) ----------------
// hg weights written ROW-PERMUTED: output row 2j <- hidden_j (k=j),
// row 2j+1 <- gate_j (k=j+DD). GEMM1 then produces interleaved hidden/gate cols.
__global__ void mix_hg_kernel(const float* __restrict__ w) {
    __shared__ float p[BB * EE];
    if (threadIdx.x < BB * EE) p[threadIdx.x] = g_probs[threadIdx.x];
    __syncthreads();
    long idx = ((long)blockIdx.x * blockDim.x + threadIdx.x) * 4;
    if (idx >= (long)K2 * DD) return;
    int k = (int)(idx / DD), d = (int)(idx % DD);
    int pr = (k < DD) ? 2 * k : 2 * (k - DD) + 1;
    long pidx = (long)pr * DD + d;
    float4 a0 = {0,0,0,0}, a1 = {0,0,0,0}, a2 = {0,0,0,0}, a3 = {0,0,0,0};
    #pragma unroll
    for (int e = 0; e < EE; e++) {
        float4 wv = *(const float4*)&w[(long)e * K2 * DD + idx];
        float p0 = p[0*EE+e], p1 = p[1*EE+e], p2 = p[2*EE+e], p3 = p[3*EE+e];
        a0.x = fmaf(p0, wv.x, a0.x); a0.y = fmaf(p0, wv.y, a0.y); a0.z = fmaf(p0, wv.z, a0.z); a0.w = fmaf(p0, wv.w, a0.w);
        a1.x = fmaf(p1, wv.x, a1.x); a1.y = fmaf(p1, wv.y, a1.y); a1.z = fmaf(p1, wv.z, a1.z); a1.w = fmaf(p1, wv.w, a1.w);
        a2.x = fmaf(p2, wv.x, a2.x); a2.y = fmaf(p2, wv.y, a2.y); a2.z = fmaf(p2, wv.z, a2.z); a2.w = fmaf(p2, wv.w, a2.w);
        a3.x = fmaf(p3, wv.x, a3.x); a3.y = fmaf(p3, wv.y, a3.y); a3.z = fmaf(p3, wv.z, a3.z); a3.w = fmaf(p3, wv.w, a3.w);
    }
    #define STH4(dst, v) do { \
        *(__half2*)&(dst)[0] = __floats2half2_rn(v.x, v.y); \
        *(__half2*)&(dst)[2] = __floats2half2_rn(v.z, v.w); } while (0)
    STH4(&g_Whg[0L * K2 * DD + pidx], a0);
    STH4(&g_Whg[1L * K2 * DD + pidx], a1);
    STH4(&g_Whg[2L * K2 * DD + pidx], a2);
    STH4(&g_Whg[3L * K2 * DD + pidx], a3);
}

__global__ void mix_out_kernel(const float* __restrict__ w) {
    __shared__ float p[BB * EE];
    if (threadIdx.x < BB * EE) p[threadIdx.x] = g_probs[threadIdx.x];
    __syncthreads();
    long idx = ((long)blockIdx.x * blockDim.x + threadIdx.x) * 4;
    if (idx >= (long)DD * DD) return;
    float4 a0 = {0,0,0,0}, a1 = {0,0,0,0}, a2 = {0,0,0,0}, a3 = {0,0,0,0};
    #pragma unroll
    for (int e = 0; e < EE; e++) {
        float4 wv = *(const float4*)&w[(long)e * DD * DD + idx];
        float p0 = p[0*EE+e], p1 = p[1*EE+e], p2 = p[2*EE+e], p3 = p[3*EE+e];
        a0.x = fmaf(p0, wv.x, a0.x); a0.y = fmaf(p0, wv.y, a0.y); a0.z = fmaf(p0, wv.z, a0.z); a0.w = fmaf(p0, wv.w, a0.w);
        a1.x = fmaf(p1, wv.x, a1.x); a1.y = fmaf(p1, wv.y, a1.y); a1.z = fmaf(p1, wv.z, a1.z); a1.w = fmaf(p1, wv.w, a1.w);
        a2.x = fmaf(p2, wv.x, a2.x); a2.y = fmaf(p2, wv.y, a2.y); a2.z = fmaf(p2, wv.z, a2.z); a2.w = fmaf(p2, wv.w, a2.w);
        a3.x = fmaf(p3, wv.x, a3.x); a3.y = fmaf(p3, wv.y, a3.y); a3.z = fmaf(p3, wv.z, a3.z); a3.w = fmaf(p3, wv.w, a3.w);
    }
    STH4(&g_Wout[0L * DD * DD + idx], a0);
    STH4(&g_Wout[1L * DD * DD + idx], a1);
    STH4(&g_Wout[2L * DD * DD + idx], a2);
    STH4(&g_Wout[3L * DD * DD + idx], a3);
}

// ---------------- fp16 mma.sync NT GEMM, templated (R13 structure) ----------------
// CV=true: N-cols interleaved (hidden_j, gate_j); epilogue stores half2 (hidden,gate).
template <int BNT, int NTN, bool CV>
__global__ __launch_bounds__(256, 2)
void gemm_fp16_kernel(const __half* __restrict__ Aall, const __half* __restrict__ Ball,
                      float* __restrict__ Call, const float* __restrict__ AddAll,
                      int N, long strideB) {
    constexpr int B_STAGE_HALVES = BNT * SPADH;
    constexpr int STAGE_HALVES = A_STAGE_HALVES + B_STAGE_HALVES;
    constexpr int STAGE_BYTES = STAGE_HALVES * 2;
    extern __shared__ __align__(16) __half smh[];
    const uint32_t sb = smem_u32(smh);
    const int K = DD;
    const int bz = blockIdx.z;
    const __half* A  = Aall + (long)bz * SS * K;
    const __half* Bm = Ball + (long)bz * strideB;
    float* C = Call ? (Call + (long)bz * SS * N) : nullptr;
    const float* Add = AddAll ? (AddAll + (long)bz * SS * N) : nullptr;

    const int tid = threadIdx.x;
    const int lane = tid & 31;
    const int w = tid >> 5;
    const int wm = w & 1;
    const int wn = w >> 1;
    const int g = lane >> 2;
    const int tg = lane & 3;

    const int row0 = blockIdx.y * BM;
    const int col0 = blockIdx.x * BNT;

    float acc[4][NTN][4];
    #pragma unroll
    for (int i = 0; i < 4; i++)
        #pragma unroll
        for (int j = 0; j < NTN; j++)
            #pragma unroll
            for (int r = 0; r < 4; r++) acc[i][j][r] = 0.f;

    auto fill = [&](int stage, int kc) {
        uint32_t abase = sb + stage * STAGE_BYTES;
        uint32_t bbase = abase + A_STAGE_HALVES * 2;
        const __half* Ak = A + kc * BK;
        #pragma unroll
        for (int i = 0; i < 4; i++) {
            int q = tid + i * 256, r = q >> 3, cg = q & 7;
            cpasync16(abase + r * (SPADH * 2) + cg * 16, Ak + (long)(row0 + r) * K + cg * 8);
        }
        const __half* Bk = Bm + kc * BK;
        #pragma unroll
        for (int i = 0; i < BNT / 32; i++) {
            int q = tid + i * 256, r = q >> 3, cg = q & 7;
            cpasync16(bbase + r * (SPADH * 2) + cg * 16, Bk + (long)(col0 + r) * K + cg * 8);
        }
        asm volatile("cp.async.commit_group;" ::: "memory");
    };

    fill(0, 0);
    fill(1, 1);

    for (int kt = 0; kt < NKC; kt++) {
        if (kt + 2 < NKC) asm volatile("cp.async.wait_group 1;" ::: "memory");
        else              asm volatile("cp.async.wait_group 0;" ::: "memory");
        __syncthreads();

        if (kt + 2 < NKC) fill((kt + 2) % NSTAGE, kt + 2);

        const __half* sA = smh + (kt % NSTAGE) * STAGE_HALVES;
        const __half* sB = sA + A_STAGE_HALVES;

        #pragma unroll
        for (int ks = 0; ks < BK; ks += 16) {
            unsigned af[4][4], bf[NTN][2];
            #pragma unroll
            for (int mt = 0; mt < 4; mt++) {
                int r = wm * 64 + mt * 16 + g;
                af[mt][0] = *(const unsigned*)&sA[r * SPADH + ks + 2 * tg];
                af[mt][1] = *(const unsigned*)&sA[(r + 8) * SPADH + ks + 2 * tg];
                af[mt][2] = *(const unsigned*)&sA[r * SPADH + ks + 2 * tg + 8];
                af[mt][3] = *(const unsigned*)&sA[(r + 8) * SPADH + ks + 2 * tg + 8];
            }
            #pragma unroll
            for (int nt = 0; nt < NTN; nt++) {
                int c = wn * (NTN * 8) + nt * 8 + g;
                bf[nt][0] = *(const unsigned*)&sB[c * SPADH + ks + 2 * tg];
                bf[nt][1] = *(const unsigned*)&sB[c * SPADH + ks + 2 * tg + 8];
            }
            #pragma unroll
            for (int mt = 0; mt < 4; mt++)
                #pragma unroll
                for (int nt = 0; nt < NTN; nt++) {
                    asm volatile(
                        "mma.sync.aligned.m16n8k16.row.col.f32.f16.f16.f32 "
                        "{%0,%1,%2,%3}, {%4,%5,%6,%7}, {%8,%9}, {%0,%1,%2,%3};\n"
                        : "+f"(acc[mt][nt][0]), "+f"(acc[mt][nt][1]),
                          "+f"(acc[mt][nt][2]), "+f"(acc[mt][nt][3])
                        : "r"(af[mt][0]), "r"(af[mt][1]), "r"(af[mt][2]), "r"(af[mt][3]),
                          "r"(bf[nt][0]), "r"(bf[nt][1]));
                }
        }
        __syncthreads();
    }

    // epilogue
    #pragma unroll
    for (int mt = 0; mt < 4; mt++) {
        int row = row0 + wm * 64 + mt * 16 + g;
        #pragma unroll
        for (int nt = 0; nt < NTN; nt++) {
            int col = col0 + wn * (NTN * 8) + nt * 8 + 2 * tg;
            if (CV) {
                // cols (col, col+1) = (hidden_j, gate_j), j = col/2; pack to half2
                int j = col >> 1;
                g_hg2[((long)bz * SS + row) * DD + j] =
                    __floats2half2_rn(acc[mt][nt][0], acc[mt][nt][1]);
                g_hg2[((long)bz * SS + row + 8) * DD + j] =
                    __floats2half2_rn(acc[mt][nt][2], acc[mt][nt][3]);
            } else {
                float2 v0 = make_float2(acc[mt][nt][0], acc[mt][nt][1]);
                float2 v1 = make_float2(acc[mt][nt][2], acc[mt][nt][3]);
                if (Add) {
                    float2 a0 = *(const float2*)&Add[(long)row * N + col];
                    float2 a1 = *(const float2*)&Add[(long)(row + 8) * N + col];
                    v0.x += a0.x; v0.y += a0.y; v1.x += a1.x; v1.y += a1.y;
                }
                *(float2*)&C[(long)row * N + col] = v0;
                *(float2*)&C[(long)(row + 8) * N + col] = v1;
            }
        }
    }
}

// ---------------- chunked scan (reads half2 hg, recomputes c,v) ----------------
__global__ void scanA_kernel() {
    int t = blockIdx.x * blockDim.x + threadIdx.x;
    if (t >= BB * NCHUNK * DD) return;
    int j = t % DD, ch = (t / DD) % NCHUNK, b = t / (DD * NCHUNK);
    long base = ((long)b * SS + (long)ch * CHUNK) * DD + j;
    float h = 0.f, Cp = 1.f;
    #pragma unroll 4
    for (int i = 0; i < CHUNK; i++) {
        float c, v;
        cv_from_h2(g_hg2[base + (long)i * DD], c, v);
        h = fmaf(c, h, v);
        Cp *= c;
    }
    g_chunkC[t] = Cp;
    g_chunkH[t] = h;
}

__global__ void scanB_kernel() {
    int t = blockIdx.x * blockDim.x + threadIdx.x;
    if (t >= BB * DD) return;
    int b = t / DD, j = t % DD;
    float hin = 0.f;
    for (int ch = 0; ch < NCHUNK; ch++) {
        int u = (b * NCHUNK + ch) * DD + j;
        g_hin[u] = hin;
        hin = fmaf(g_chunkC[u], hin, g_chunkH[u]);
    }
}

__global__ void scanC_kernel(float* __restrict__ out) {
    int t = blockIdx.x * blockDim.x + threadIdx.x;
    if (t >= BB * NCHUNK * DD) return;
    int j = t % DD, ch = (t / DD) % NCHUNK, b = t / (DD * NCHUNK);
    long base = ((long)b * SS + (long)ch * CHUNK) * DD + j;
    float h = g_hin[t];
    #pragma unroll 4
    for (int i = 0; i < CHUNK; i++) {
        float c, v;
        cv_from_h2(g_hg2[base + (long)i * DD], c, v);
        h = fmaf(c, h, v);
        g_h[base + (long)i * DD] = __float2half_rn(h);
    }
    if (ch == NCHUNK - 1) out[(long)BB * SS * DD + b * DD + j] = h;  // new_state
    if (t == 0) out[(long)BB * SS * DD + BB * DD] = 0.f;             // aux_loss
}

// ---------------- launch ----------------
extern "C" void kernel_launch(void* const* d_in, const int* in_sizes, int n_in,
                              void* d_out, int out_size) {
    const float* inputs   = (const float*)d_in[0];
    const float* norm_w   = (const float*)d_in[1];
    const float* router_w = (const float*)d_in[2];
    const float* router_b = (const float*)d_in[3];
    const float* w_hg     = (const float*)d_in[4];
    const float* w_out    = (const float*)d_in[5];
    float* out = (float*)d_out;

    __half* x_p;    cudaGetSymbolAddress((void**)&x_p, g_x);
    __half* Whg_p;  cudaGetSymbolAddress((void**)&Whg_p, g_Whg);
    __half* Wout_p; cudaGetSymbolAddress((void**)&Wout_p, g_Wout);
    __half* h_p;    cudaGetSymbolAddress((void**)&h_p, g_h);

    constexpr int SMEMB = NSTAGE * (A_STAGE_HALVES + 128 * SPADH) * 2;  // 110592
    cudaFuncSetAttribute((const void*)gemm_fp16_kernel<128, 4, true>,
                         cudaFuncAttributeMaxDynamicSharedMemorySize, SMEMB);
    cudaFuncSetAttribute((const void*)gemm_fp16_kernel<128, 4, false>,
                         cudaFuncAttributeMaxDynamicSharedMemorySize, SMEMB);

    // one-time side-stream resources (created once; identical work every call)
    static cudaStream_t side = nullptr;
    static cudaEvent_t evFork = nullptr, evJoin = nullptr;
    if (!side) {
        cudaStreamCreateWithFlags(&side, cudaStreamNonBlocking);
        cudaEventCreateWithFlags(&evFork, cudaEventDisableTiming);
        cudaEventCreateWithFlags(&evJoin, cudaEventDisableTiming);
    }

    rmsnorm_kernel<<<BB * SS, 256>>>(inputs, norm_w);
    colmean_kernel<<<(BB * DD + 255) / 256, 256>>>();
    router_kernel<<<1, 256>>>(router_w, router_b);

    // fork: mix_out runs on side stream, hidden under mix_hg + GEMM1 + scans
    cudaEventRecord(evFork, 0);
    cudaStreamWaitEvent(side, evFork, 0);
    mix_out_kernel<<<(DD * DD / 4) / 256, 256, 0, side>>>(w_out);
    cudaEventRecord(evJoin, side);

    mix_hg_kernel<<<(K2 * DD / 4) / 256, 256>>>(w_hg);

    // GEMM1: hg = x @ Whg^T with interleaved cols; epilogue emits half2 (hidden,gate)
    gemm_fp16_kernel<128, 4, true><<<dim3(K2 / 128, SS / BM, BB), 256, SMEMB>>>(
        x_p, Whg_p, nullptr, nullptr, K2, (long)K2 * DD);

    scanA_kernel<<<(BB * NCHUNK * DD + 255) / 256, 256>>>();
    scanB_kernel<<<(BB * DD + 255) / 256, 256>>>();
    scanC_kernel<<<(BB * NCHUNK * DD + 255) / 256, 256>>>(out);

    // join: GEMM2 needs mix_out's weights
    cudaStreamWaitEvent(0, evJoin, 0);

    // GEMM2: out = h @ Wout^T + inputs
    gemm_fp16_kernel<128, 4, false><<<dim3(DD / 128, SS / BM, BB), 256, SMEMB>>>(
        h_p, Wout_p, out, inputs, DD, (long)DD * DD);
}

// round 17
// speedup vs baseline: 1.0966x; 1.0966x over previous
#include <cuda_runtime.h>
#include <cuda_fp16.h>
#include <math.h>
#include <stdint.h>

#define BB 4
#define SS 2048
#define DD 1024
#define EE 8
#define K2 2048
#define EPSV 1e-6f
#define NCHUNK 16
#define CHUNK (SS / NCHUNK)   // 128

// ---------------- GEMM tiling (fp16 operands) ----------------
#define BM 128
#define BK 64                     // halves per K-chunk (128 bytes/row)
#define NKC (DD / BK)             // 16
#define SPADH 72                  // smem row stride in halves (64 + 8)
#define A_STAGE_HALVES (BM * SPADH)              // 9216
#define NSTAGE 3

// ---------------- scratch ----------------
__device__ __half g_x[BB * SS * DD];
__device__ float  g_xmean[BB * DD];
__device__ float  g_probs[BB * EE];
__device__ __half g_Whg[BB * K2 * DD];    // row-permuted: 2j=hidden_j, 2j+1=gate_j
__device__ __half g_Wout[BB * DD * DD];
__device__ float  g_c[BB * SS * DD];
__device__ float  g_v[BB * SS * DD];
__device__ __half g_h[BB * SS * DD];
__device__ float  g_chunkC[BB * NCHUNK * DD];
__device__ float  g_chunkH[BB * NCHUNK * DD];

// ---------------- helpers ----------------
__device__ __forceinline__ uint32_t smem_u32(const void* p) {
    uint32_t a;
    asm("{ .reg .u64 t; cvta.to.shared.u64 t, %1; cvt.u32.u64 %0, t; }" : "=r"(a) : "l"(p));
    return a;
}
__device__ __forceinline__ void cpasync16(uint32_t dst, const void* src) {
    asm volatile("cp.async.cg.shared.global [%0], [%1], 16;" :: "r"(dst), "l"(src));
}
// c = sigmoid(-gate); v = sigmoid(gate) * (hidden>=0 ? hidden+0.5 : sigmoid(hidden))
__device__ __forceinline__ void cv_from_hg(float hidden, float gate, float& c, float& v) {
    float t = expf(-fabsf(gate));
    float inv = 1.0f / (1.0f + t);
    float sp;
    if (gate >= 0.f) { sp = inv; c = t * inv; }
    else             { sp = t * inv; c = inv; }
    float gh = (hidden >= 0.f) ? (hidden + 0.5f) : (1.0f / (1.0f + expf(-hidden)));
    v = sp * gh;
}

// ---------------- 1. RMSNorm (writes fp16 x) ----------------
__global__ void rmsnorm_kernel(const float* __restrict__ inp, const float* __restrict__ nw) {
    int row = blockIdx.x;
    const float* in = inp + (long)row * DD;
    __half* out = g_x + (long)row * DD;
    float ss = 0.f;
    for (int d = threadIdx.x; d < DD; d += 256) { float t = in[d]; ss += t * t; }
    __shared__ float red[256];
    red[threadIdx.x] = ss; __syncthreads();
    for (int s = 128; s > 0; s >>= 1) {
        if (threadIdx.x < s) red[threadIdx.x] += red[threadIdx.x + s];
        __syncthreads();
    }
    float scale = rsqrtf(red[0] * (1.0f / DD) + EPSV);
    for (int d = threadIdx.x; d < DD; d += 256) out[d] = __float2half_rn(in[d] * scale * nw[d]);
}

// ---------------- 2. column mean ----------------
__global__ void colmean_kernel() {
    int t = blockIdx.x * blockDim.x + threadIdx.x;
    if (t >= BB * DD) return;
    int b = t / DD, d = t % DD;
    float s = 0.f;
    const __half* base = g_x + (long)b * SS * DD + d;
    for (int i = 0; i < SS; i++) s += __half2float(base[(long)i * DD]);
    g_xmean[t] = s * (1.0f / SS);
}

// ---------------- 3. router ----------------
__global__ void router_kernel(const float* __restrict__ rw, const float* __restrict__ rb) {
    __shared__ float logits[BB * EE];
    int tid = threadIdx.x, warp = tid / 32, lane = tid % 32;
    for (int p = warp; p < BB * EE; p += 8) {
        int b = p / EE, e = p % EE;
        float s = 0.f;
        for (int d = lane; d < DD; d += 32) s += g_xmean[b * DD + d] * rw[e * DD + d];
        for (int o = 16; o > 0; o >>= 1) s += __shfl_xor_sync(0xffffffffu, s, o);
        if (lane == 0) logits[p] = s + rb[e];
    }
    __syncthreads();
    if (tid < BB) {
        float mx = -1e30f;
        for (int e = 0; e < EE; e++) mx = fmaxf(mx, logits[tid * EE + e]);
        float ex[EE]; float sum = 0.f;
        for (int e = 0; e < EE; e++) { ex[e] = expf(logits[tid * EE + e] - mx); sum += ex[e]; }
        float inv = 1.0f / sum;
        for (int e = 0; e < EE; e++) g_probs[tid * EE + e] = ex[e] * inv;
    }
}

// ---------------- 4. mix expert weights (fp32 accum, fp16 out) ----------------
// hg weights written ROW-PERMUTED: output row 2j <- hidden_j (k=j),
// row 2j+1 <- gate_j (k=j+DD). GEMM1 then produces interleaved hidden/gate cols.
__global__ void mix_hg_kernel(const float* __restrict__ w) {
    __shared__ float p[BB * EE];
    if (threadIdx.x < BB * EE) p[threadIdx.x] = g_probs[threadIdx.x];
    __syncthreads();
    long idx = ((long)blockIdx.x * blockDim.x + threadIdx.x) * 4;
    if (idx >= (long)K2 * DD) return;
    int k = (int)(idx / DD), d = (int)(idx % DD);
    int pr = (k < DD) ? 2 * k : 2 * (k - DD) + 1;
    long pidx = (long)pr * DD + d;
    float4 a0 = {0,0,0,0}, a1 = {0,0,0,0}, a2 = {0,0,0,0}, a3 = {0,0,0,0};
    #pragma unroll
    for (int e = 0; e < EE; e++) {
        float4 wv = *(const float4*)&w[(long)e * K2 * DD + idx];
        float p0 = p[0*EE+e], p1 = p[1*EE+e], p2 = p[2*EE+e], p3 = p[3*EE+e];
        a0.x = fmaf(p0, wv.x, a0.x); a0.y = fmaf(p0, wv.y, a0.y); a0.z = fmaf(p0, wv.z, a0.z); a0.w = fmaf(p0, wv.w, a0.w);
        a1.x = fmaf(p1, wv.x, a1.x); a1.y = fmaf(p1, wv.y, a1.y); a1.z = fmaf(p1, wv.z, a1.z); a1.w = fmaf(p1, wv.w, a1.w);
        a2.x = fmaf(p2, wv.x, a2.x); a2.y = fmaf(p2, wv.y, a2.y); a2.z = fmaf(p2, wv.z, a2.z); a2.w = fmaf(p2, wv.w, a2.w);
        a3.x = fmaf(p3, wv.x, a3.x); a3.y = fmaf(p3, wv.y, a3.y); a3.z = fmaf(p3, wv.z, a3.z); a3.w = fmaf(p3, wv.w, a3.w);
    }
    #define STH4(dst, v) do { \
        *(__half2*)&(dst)[0] = __floats2half2_rn(v.x, v.y); \
        *(__half2*)&(dst)[2] = __floats2half2_rn(v.z, v.w); } while (0)
    STH4(&g_Whg[0L * K2 * DD + pidx], a0);
    STH4(&g_Whg[1L * K2 * DD + pidx], a1);
    STH4(&g_Whg[2L * K2 * DD + pidx], a2);
    STH4(&g_Whg[3L * K2 * DD + pidx], a3);
}

__global__ void mix_out_kernel(const float* __restrict__ w) {
    __shared__ float p[BB * EE];
    if (threadIdx.x < BB * EE) p[threadIdx.x] = g_probs[threadIdx.x];
    __syncthreads();
    long idx = ((long)blockIdx.x * blockDim.x + threadIdx.x) * 4;
    if (idx >= (long)DD * DD) return;
    float4 a0 = {0,0,0,0}, a1 = {0,0,0,0}, a2 = {0,0,0,0}, a3 = {0,0,0,0};
    #pragma unroll
    for (int e = 0; e < EE; e++) {
        float4 wv = *(const float4*)&w[(long)e * DD * DD + idx];
        float p0 = p[0*EE+e], p1 = p[1*EE+e], p2 = p[2*EE+e], p3 = p[3*EE+e];
        a0.x = fmaf(p0, wv.x, a0.x); a0.y = fmaf(p0, wv.y, a0.y); a0.z = fmaf(p0, wv.z, a0.z); a0.w = fmaf(p0, wv.w, a0.w);
        a1.x = fmaf(p1, wv.x, a1.x); a1.y = fmaf(p1, wv.y, a1.y); a1.z = fmaf(p1, wv.z, a1.z); a1.w = fmaf(p1, wv.w, a1.w);
        a2.x = fmaf(p2, wv.x, a2.x); a2.y = fmaf(p2, wv.y, a2.y); a2.z = fmaf(p2, wv.z, a2.z); a2.w = fmaf(p2, wv.w, a2.w);
        a3.x = fmaf(p3, wv.x, a3.x); a3.y = fmaf(p3, wv.y, a3.y); a3.z = fmaf(p3, wv.z, a3.z); a3.w = fmaf(p3, wv.w, a3.w);
    }
    STH4(&g_Wout[0L * DD * DD + idx], a0);
    STH4(&g_Wout[1L * DD * DD + idx], a1);
    STH4(&g_Wout[2L * DD * DD + idx], a2);
    STH4(&g_Wout[3L * DD * DD + idx], a3);
}

// ---------------- fp16 mma.sync NT GEMM, templated (R13 structure) ----------------
// BNT=128 CTA N-tile, 2 CTAs/SM. Warp tile 64 x 8*NTN.
// CV=true: N-cols interleaved (hidden_j, gate_j); epilogue computes c,v.
template <int BNT, int NTN, bool CV>
__global__ __launch_bounds__(256, 2)
void gemm_fp16_kernel(const __half* __restrict__ Aall, const __half* __restrict__ Ball,
                      float* __restrict__ Call, const float* __restrict__ AddAll,
                      int N, long strideB) {
    constexpr int B_STAGE_HALVES = BNT * SPADH;
    constexpr int STAGE_HALVES = A_STAGE_HALVES + B_STAGE_HALVES;
    constexpr int STAGE_BYTES = STAGE_HALVES * 2;
    extern __shared__ __align__(16) __half smh[];
    const uint32_t sb = smem_u32(smh);
    const int K = DD;
    const int bz = blockIdx.z;
    const __half* A  = Aall + (long)bz * SS * K;
    const __half* Bm = Ball + (long)bz * strideB;
    float* C = Call ? (Call + (long)bz * SS * N) : nullptr;
    const float* Add = AddAll ? (AddAll + (long)bz * SS * N) : nullptr;

    const int tid = threadIdx.x;
    const int lane = tid & 31;
    const int w = tid >> 5;
    const int wm = w & 1;
    const int wn = w >> 1;
    const int g = lane >> 2;
    const int tg = lane & 3;

    const int row0 = blockIdx.y * BM;
    const int col0 = blockIdx.x * BNT;

    float acc[4][NTN][4];
    #pragma unroll
    for (int i = 0; i < 4; i++)
        #pragma unroll
        for (int j = 0; j < NTN; j++)
            #pragma unroll
            for (int r = 0; r < 4; r++) acc[i][j][r] = 0.f;

    auto fill = [&](int stage, int kc) {
        uint32_t abase = sb + stage * STAGE_BYTES;
        uint32_t bbase = abase + A_STAGE_HALVES * 2;
        const __half* Ak = A + kc * BK;
        #pragma unroll
        for (int i = 0; i < 4; i++) {
            int q = tid + i * 256, r = q >> 3, cg = q & 7;
            cpasync16(abase + r * (SPADH * 2) + cg * 16, Ak + (long)(row0 + r) * K + cg * 8);
        }
        const __half* Bk = Bm + kc * BK;
        #pragma unroll
        for (int i = 0; i < BNT / 32; i++) {
            int q = tid + i * 256, r = q >> 3, cg = q & 7;
            cpasync16(bbase + r * (SPADH * 2) + cg * 16, Bk + (long)(col0 + r) * K + cg * 8);
        }
        asm volatile("cp.async.commit_group;" ::: "memory");
    };

    fill(0, 0);
    fill(1, 1);

    for (int kt = 0; kt < NKC; kt++) {
        if (kt + 2 < NKC) asm volatile("cp.async.wait_group 1;" ::: "memory");
        else              asm volatile("cp.async.wait_group 0;" ::: "memory");
        __syncthreads();

        if (kt + 2 < NKC) fill((kt + 2) % NSTAGE, kt + 2);

        const __half* sA = smh + (kt % NSTAGE) * STAGE_HALVES;
        const __half* sB = sA + A_STAGE_HALVES;

        #pragma unroll
        for (int ks = 0; ks < BK; ks += 16) {
            unsigned af[4][4], bf[NTN][2];
            #pragma unroll
            for (int mt = 0; mt < 4; mt++) {
                int r = wm * 64 + mt * 16 + g;
                af[mt][0] = *(const unsigned*)&sA[r * SPADH + ks + 2 * tg];
                af[mt][1] = *(const unsigned*)&sA[(r + 8) * SPADH + ks + 2 * tg];
                af[mt][2] = *(const unsigned*)&sA[r * SPADH + ks + 2 * tg + 8];
                af[mt][3] = *(const unsigned*)&sA[(r + 8) * SPADH + ks + 2 * tg + 8];
            }
            #pragma unroll
            for (int nt = 0; nt < NTN; nt++) {
                int c = wn * (NTN * 8) + nt * 8 + g;
                bf[nt][0] = *(const unsigned*)&sB[c * SPADH + ks + 2 * tg];
                bf[nt][1] = *(const unsigned*)&sB[c * SPADH + ks + 2 * tg + 8];
            }
            #pragma unroll
            for (int mt = 0; mt < 4; mt++)
                #pragma unroll
                for (int nt = 0; nt < NTN; nt++) {
                    asm volatile(
                        "mma.sync.aligned.m16n8k16.row.col.f32.f16.f16.f32 "
                        "{%0,%1,%2,%3}, {%4,%5,%6,%7}, {%8,%9}, {%0,%1,%2,%3};\n"
                        : "+f"(acc[mt][nt][0]), "+f"(acc[mt][nt][1]),
                          "+f"(acc[mt][nt][2]), "+f"(acc[mt][nt][3])
                        : "r"(af[mt][0]), "r"(af[mt][1]), "r"(af[mt][2]), "r"(af[mt][3]),
                          "r"(bf[nt][0]), "r"(bf[nt][1]));
                }
        }
        __syncthreads();
    }

    // epilogue
    #pragma unroll
    for (int mt = 0; mt < 4; mt++) {
        int row = row0 + wm * 64 + mt * 16 + g;
        #pragma unroll
        for (int nt = 0; nt < NTN; nt++) {
            int col = col0 + wn * (NTN * 8) + nt * 8 + 2 * tg;
            if (CV) {
                // cols (col, col+1) = (hidden_j, gate_j), j = col/2
                int j = col >> 1;
                long base0 = ((long)bz * SS + row) * DD + j;
                long base1 = ((long)bz * SS + row + 8) * DD + j;
                float c0, v0, c1, v1;
                cv_from_hg(acc[mt][nt][0], acc[mt][nt][1], c0, v0);
                cv_from_hg(acc[mt][nt][2], acc[mt][nt][3], c1, v1);
                g_c[base0] = c0; g_v[base0] = v0;
                g_c[base1] = c1; g_v[base1] = v1;
            } else {
                float2 v0 = make_float2(acc[mt][nt][0], acc[mt][nt][1]);
                float2 v1 = make_float2(acc[mt][nt][2], acc[mt][nt][3]);
                if (Add) {
                    float2 a0 = *(const float2*)&Add[(long)row * N + col];
                    float2 a1 = *(const float2*)&Add[(long)(row + 8) * N + col];
                    v0.x += a0.x; v0.y += a0.y; v1.x += a1.x; v1.y += a1.y;
                }
                *(float2*)&C[(long)row * N + col] = v0;
                *(float2*)&C[(long)(row + 8) * N + col] = v1;
            }
        }
    }
}

// ---------------- chunked scan (pure memory) ----------------
__global__ void scanA_kernel() {
    int t = blockIdx.x * blockDim.x + threadIdx.x;
    if (t >= BB * NCHUNK * DD) return;
    int j = t % DD, ch = (t / DD) % NCHUNK, b = t / (DD * NCHUNK);
    long base = ((long)b * SS + (long)ch * CHUNK) * DD + j;
    float h = 0.f, Cp = 1.f;
    #pragma unroll 4
    for (int i = 0; i < CHUNK; i++) {
        float c = g_c[base + (long)i * DD];
        float v = g_v[base + (long)i * DD];
        h = fmaf(c, h, v);
        Cp *= c;
    }
    g_chunkC[t] = Cp;
    g_chunkH[t] = h;
}

// scanC with scanB merged: each thread re-derives hin from the chunk stats
// (same fma order as the old scanB -> bit-identical results).
__global__ void scanC_kernel(float* __restrict__ out) {
    int t = blockIdx.x * blockDim.x + threadIdx.x;
    if (t >= BB * NCHUNK * DD) return;
    int j = t % DD, ch = (t / DD) % NCHUNK, b = t / (DD * NCHUNK);

    float h = 0.f;
    for (int cc = 0; cc < ch; cc++) {    // uniform per block (j fastest, DD >= blockDim)
        int u = (b * NCHUNK + cc) * DD + j;
        h = fmaf(g_chunkC[u], h, g_chunkH[u]);
    }

    long base = ((long)b * SS + (long)ch * CHUNK) * DD + j;
    #pragma unroll 4
    for (int i = 0; i < CHUNK; i++) {
        float c = g_c[base + (long)i * DD];
        float v = g_v[base + (long)i * DD];
        h = fmaf(c, h, v);
        g_h[base + (long)i * DD] = __float2half_rn(h);
    }
    if (ch == NCHUNK - 1) out[(long)BB * SS * DD + b * DD + j] = h;  // new_state
    if (t == 0) out[(long)BB * SS * DD + BB * DD] = 0.f;             // aux_loss
}

// ---------------- launch ----------------
extern "C" void kernel_launch(void* const* d_in, const int* in_sizes, int n_in,
                              void* d_out, int out_size) {
    const float* inputs   = (const float*)d_in[0];
    const float* norm_w   = (const float*)d_in[1];
    const float* router_w = (const float*)d_in[2];
    const float* router_b = (const float*)d_in[3];
    const float* w_hg     = (const float*)d_in[4];
    const float* w_out    = (const float*)d_in[5];
    float* out = (float*)d_out;

    __half* x_p;    cudaGetSymbolAddress((void**)&x_p, g_x);
    __half* Whg_p;  cudaGetSymbolAddress((void**)&Whg_p, g_Whg);
    __half* Wout_p; cudaGetSymbolAddress((void**)&Wout_p, g_Wout);
    __half* h_p;    cudaGetSymbolAddress((void**)&h_p, g_h);

    constexpr int SMEMB = NSTAGE * (A_STAGE_HALVES + 128 * SPADH) * 2;  // 110592
    cudaFuncSetAttribute((const void*)gemm_fp16_kernel<128, 4, true>,
                         cudaFuncAttributeMaxDynamicSharedMemorySize, SMEMB);
    cudaFuncSetAttribute((const void*)gemm_fp16_kernel<128, 4, false>,
                         cudaFuncAttributeMaxDynamicSharedMemorySize, SMEMB);

    // one-time side-stream resources (created on the uncaptured correctness run)
    static cudaStream_t side = nullptr;
    static cudaEvent_t evFork = nullptr, evJoin = nullptr;
    if (!side) {
        cudaStreamCreateWithFlags(&side, cudaStreamNonBlocking);
        cudaEventCreateWithFlags(&evFork, cudaEventDisableTiming);
        cudaEventCreateWithFlags(&evJoin, cudaEventDisableTiming);
    }

    rmsnorm_kernel<<<BB * SS, 256>>>(inputs, norm_w);
    colmean_kernel<<<(BB * DD + 255) / 256, 256>>>();
    router_kernel<<<1, 256>>>(router_w, router_b);

    // fork: mix_out overlaps mix_hg + GEMM1 + scans
    cudaEventRecord(evFork, 0);
    cudaStreamWaitEvent(side, evFork, 0);
    mix_out_kernel<<<(DD * DD / 4) / 256, 256, 0, side>>>(w_out);
    cudaEventRecord(evJoin, side);

    mix_hg_kernel<<<(K2 * DD / 4) / 256, 256>>>(w_hg);

    // GEMM1: hg = x @ Whg^T with interleaved cols; epilogue emits c,v
    gemm_fp16_kernel<128, 4, true><<<dim3(K2 / 128, SS / BM, BB), 256, SMEMB>>>(
        x_p, Whg_p, nullptr, nullptr, K2, (long)K2 * DD);

    scanA_kernel<<<(BB * NCHUNK * DD + 255) / 256, 256>>>();
    scanC_kernel<<<(BB * NCHUNK * DD + 255) / 256, 256>>>(out);

    // join: GEMM2 needs mix_out's weights
    cudaStreamWaitEvent(0, evJoin, 0);

    // GEMM2: out = h @ Wout^T + inputs
    gemm_fp16_kernel<128, 4, false><<<dim3(DD / 128, SS / BM, BB), 256, SMEMB>>>(
        h_p, Wout_p, out, inputs, DD, (long)DD * DD);
}